// round 8
// baseline (speedup 1.0000x reference)
#include <cuda_runtime.h>
#include <cuda_bf16.h>
#include <cstdint>

// Problem constants
#define BATCH 16
#define HGRID 64
#define WGRID 64
#define DIM   512
#define NTOK  (1 + HGRID * WGRID)     // 4097

// Tiling: 16x16 spatial tile, 32 channels (16 ull lanes)
#define CT        32
#define LANES     16
#define TILE      16
#define TIN       22                  // TILE + 6 halo
#define SPOS      (TIN * TIN)         // 484
#define SP        486                 // lane stride (ull): 486*8 mod 128 = 48 -> conflict-free
#define WP        58                  // weight lane stride: 58*8 mod 128 = 80 -> conflict-free
#define NW        49
#define THREADS   256

#define SMEM_ULL   (LANES * SP + LANES * WP)      // 7776 + 928 = 8704
#define SMEM_BYTES (SMEM_ULL * 8)                 // 69632

typedef unsigned long long ull;

__device__ __forceinline__ ull fma2(ull a, ull b, ull c) {
    ull d;
    asm("fma.rn.f32x2 %0, %1, %2, %3;" : "=l"(d) : "l"(a), "l"(b), "l"(c));
    return d;
}

__device__ __forceinline__ ull pack2(float lo, float hi) {
    ull d;
    asm("mov.b64 %0, {%1, %2};" : "=l"(d) : "f"(lo), "f"(hi));
    return d;
}

// ---------------------------------------------------------------------------
// Single fused kernel: weight fusion + cls copy + 7x7 depthwise conv.
// grid: (16 channel groups, 4x4 spatial tiles, 16 batch), 256 threads.
// Each thread: 2 rows x 8 cols x 2 channels. Input rows double-buffered in
// registers (prefetch next row before computing current); single weight-row
// buffer consumed-then-reloaded to keep live regs ~114 (< 128 cap).
// ---------------------------------------------------------------------------
__global__ void __launch_bounds__(THREADS, 2)
conv_kernel(const float* __restrict__ x,
            const float* __restrict__ w7, const float* __restrict__ b7,
            const float* __restrict__ w5, const float* __restrict__ b5,
            const float* __restrict__ w3, const float* __restrict__ b3,
            float* __restrict__ out) {
    extern __shared__ ull sm[];
    ull* s_in = sm;                    // [LANES][SP]  pos-major per lane
    ull* s_w  = sm + LANES * SP;       // [LANES][WP]  8 slots per kr row

    const int tid  = threadIdx.x;
    const int lane = tid & (LANES - 1);
    const int pg   = tid >> 4;                     // 0..15

    const int c0 = blockIdx.x * CT;
    const int h0 = (blockIdx.y >> 2) * TILE;
    const int w0 = (blockIdx.y & 3) * TILE;
    const int b  = blockIdx.z;

    const ull* x64 = (const ull*)x;
    ull* o64       = (ull*)out;
    const int cl      = (c0 >> 1) + lane;
    const int tokbase = b * NTOK + 1;              // skip cls token

    // --- Fuse weights: w7 + pad(w5) + pad(w3) + identity ---
    #pragma unroll 1
    for (int s = tid; s < NW * LANES; s += THREADS) {
        const int k  = s >> 4;
        const int sl = s & (LANES - 1);
        const int kr = k / 7, kc = k - kr * 7;
        const int c  = c0 + 2 * sl;
        float v0 = w7[c * 49 + k];
        float v1 = w7[(c + 1) * 49 + k];
        if (kr >= 1 && kr <= 5 && kc >= 1 && kc <= 5) {
            const int k5 = (kr - 1) * 5 + (kc - 1);
            v0 += w5[c * 25 + k5];
            v1 += w5[(c + 1) * 25 + k5];
        }
        if (kr >= 2 && kr <= 4 && kc >= 2 && kc <= 4) {
            const int k3 = (kr - 2) * 3 + (kc - 2);
            v0 += w3[c * 9 + k3];
            v1 += w3[(c + 1) * 9 + k3];
        }
        if (kr == 3 && kc == 3) { v0 += 1.0f; v1 += 1.0f; }
        s_w[sl * WP + kr * 8 + kc] = pack2(v0, v1);
    }

    // --- cls token pass-through ---
    if (blockIdx.y == 0 && tid < LANES) {
        const int off = (b * NTOK) * (DIM / 2) + (c0 >> 1) + tid;
        o64[off] = x64[off];
    }

    // --- Stage input tile (22x22 x 32ch), pos-major, zero-padded halo ---
    {
        const ull* xb = x64 + (size_t)tokbase * (DIM / 2) + cl;
        ull* sp = s_in + lane * SP;

        int col = pg;                  // 0..15 < TIN
        int gh  = h0 - 3;
        int off = gh * WGRID + (w0 - 3 + col);

        #pragma unroll 4
        for (int p = pg; p < SPOS; p += 16) {
            const int gw = w0 - 3 + col;
            ull v = 0ull;
            if ((unsigned)gh < (unsigned)HGRID && (unsigned)gw < (unsigned)WGRID)
                v = xb[(long)off * (DIM / 2)];
            sp[p] = v;
            col += 16; off += 16;
            if (col >= TIN) { col -= TIN; gh++; off += WGRID - TIN; }
        }
    }

    // --- Bias ---
    const int cb = c0 + 2 * lane;
    const ull bv = pack2(b7[cb] + b5[cb] + b3[cb],
                         b7[cb + 1] + b5[cb + 1] + b3[cb + 1]);

    __syncthreads();

    // --- Each thread: 2 rows x 8 cols, 2 channels ---
    const int y   = tid >> 4;           // 0..15
    const int rp  = y & 7;              // row pair 0..7
    const int q0  = (y >> 3) * 8;       // col half: 0 or 8
    const int or0 = 2 * rp;

    const ull* inb = s_in + lane * SP + q0;
    const ull* wb  = s_w + lane * WP;

    ull a0[8], a1[8];
    #pragma unroll
    for (int c = 0; c < 8; ++c) { a0[c] = bv; a1[c] = bv; }

    ull in2[2][14];                     // double-buffered input rows
    ull wbuf[8];                        // single weight-row buffer

    // Preload input row 0
    {
        const ulonglong2* ip = (const ulonglong2*)(inb + or0 * TIN);
        #pragma unroll
        for (int j = 0; j < 7; ++j) {
            ulonglong2 v = ip[j];
            in2[0][2 * j] = v.x; in2[0][2 * j + 1] = v.y;
        }
    }

    #pragma unroll
    for (int ir = 0; ir < 8; ++ir) {    // input rows or0 .. or0+7
        const int cur = ir & 1;
        // 1) Prefetch next input row (hides LDS latency under FFMA2s below)
        if (ir < 7) {
            const ulonglong2* ip = (const ulonglong2*)(inb + (or0 + ir + 1) * TIN);
            #pragma unroll
            for (int j = 0; j < 7; ++j) {
                ulonglong2 v = ip[j];
                in2[cur ^ 1][2 * j] = v.x; in2[cur ^ 1][2 * j + 1] = v.y;
            }
        }
        // 2) a1 consumes wbuf (= weight row ir-1) before it is overwritten
        if (ir >= 1) {
            #pragma unroll
            for (int kc = 0; kc < 7; ++kc)
                #pragma unroll
                for (int c = 0; c < 8; ++c)
                    a1[c] = fma2(in2[cur][c + kc], wbuf[kc], a1[c]);
        }
        // 3) Reload wbuf with weight row ir
        if (ir <= 6) {
            const ulonglong2* wp2 = (const ulonglong2*)(wb + ir * 8);
            #pragma unroll
            for (int j = 0; j < 4; ++j) {
                ulonglong2 v = wp2[j];
                wbuf[2 * j] = v.x; wbuf[2 * j + 1] = v.y;
            }
            // 4) a0 uses the fresh weight row
            #pragma unroll
            for (int kc = 0; kc < 7; ++kc)
                #pragma unroll
                for (int c = 0; c < 8; ++c)
                    a0[c] = fma2(in2[cur][c + kc], wbuf[kc], a0[c]);
        }
    }

    // --- Store 2 rows x 8 cols ---
    const int row0 = (tokbase + (h0 + or0) * WGRID + (w0 + q0)) * (DIM / 2) + cl;
    const int row1 = row0 + WGRID * (DIM / 2);
    #pragma unroll
    for (int c = 0; c < 8; ++c) {
        o64[row0 + c * (DIM / 2)] = a0[c];
        o64[row1 + c * (DIM / 2)] = a1[c];
    }
}

// ---------------------------------------------------------------------------
extern "C" void kernel_launch(void* const* d_in, const int* in_sizes, int n_in,
                              void* d_out, int out_size) {
    const float* x  = (const float*)d_in[0];
    const float* w7 = (const float*)d_in[1];
    const float* b7 = (const float*)d_in[2];
    const float* w5 = (const float*)d_in[3];
    const float* b5 = (const float*)d_in[4];
    const float* w3 = (const float*)d_in[5];
    const float* b3 = (const float*)d_in[6];
    float* out = (float*)d_out;

    cudaFuncSetAttribute(conv_kernel,
                         cudaFuncAttributeMaxDynamicSharedMemorySize, SMEM_BYTES);

    dim3 grid(DIM / CT, (HGRID / TILE) * (WGRID / TILE), BATCH);  // 16,16,16
    conv_kernel<<<grid, THREADS, SMEM_BYTES>>>(x, w7, b7, w5, b5, w3, b3, out);
}

// round 9
// speedup vs baseline: 1.1229x; 1.1229x over previous
#include <cuda_runtime.h>
#include <cuda_bf16.h>
#include <cstdint>

// Problem constants
#define BATCH 16
#define HGRID 64
#define WGRID 64
#define DIM   512
#define NTOK  (1 + HGRID * WGRID)     // 4097

// Tiling: 16x16 spatial tile, 32 channels (16 ull lanes)
#define CT        32
#define LANES     16
#define TILE      16
#define TIN       22                  // TILE + 6 halo
#define SPOS      (TIN * TIN)         // 484
#define SP        486                 // lane stride (ull): 486*8 mod 128 = 48 -> conflict-free
#define WP        58                  // weight lane stride: 58*8 mod 128 = 80 -> conflict-free
#define NW        49
#define THREADS   256

#define SMEM_ULL   (LANES * SP + LANES * WP)      // 7776 + 928 = 8704
#define SMEM_BYTES (SMEM_ULL * 8)                 // 69632

typedef unsigned long long ull;

__device__ __forceinline__ ull pack2(float lo, float hi) {
    ull d;
    asm("mov.b64 %0, {%1, %2};" : "=l"(d) : "f"(lo), "f"(hi));
    return d;
}

// ---------------------------------------------------------------------------
// Single fused kernel: weight fusion + cls copy + 7x7 depthwise conv.
// grid: (16 channel groups, 4x4 spatial tiles, 16 batch), 256 threads.
// Each thread: 2 rows x 8 cols x 2 channels. Math in scalar FFMA (rt=2)
// instead of packed f32x2 (measured ceiling ~0.68 inst/cyc/SM).
// ---------------------------------------------------------------------------
__global__ void __launch_bounds__(THREADS, 2)
conv_kernel(const float* __restrict__ x,
            const float* __restrict__ w7, const float* __restrict__ b7,
            const float* __restrict__ w5, const float* __restrict__ b5,
            const float* __restrict__ w3, const float* __restrict__ b3,
            float* __restrict__ out) {
    extern __shared__ ull sm[];
    ull* s_in = sm;                    // [LANES][SP]  pos-major per lane
    ull* s_w  = sm + LANES * SP;       // [LANES][WP]  8 slots per kr row

    const int tid  = threadIdx.x;
    const int lane = tid & (LANES - 1);
    const int pg   = tid >> 4;                     // 0..15

    const int c0 = blockIdx.x * CT;
    const int h0 = (blockIdx.y >> 2) * TILE;
    const int w0 = (blockIdx.y & 3) * TILE;
    const int b  = blockIdx.z;

    const ull* x64 = (const ull*)x;
    ull* o64       = (ull*)out;
    const int cl      = (c0 >> 1) + lane;
    const int tokbase = b * NTOK + 1;              // skip cls token

    // --- Fuse weights: w7 + pad(w5) + pad(w3) + identity ---
    #pragma unroll 1
    for (int s = tid; s < NW * LANES; s += THREADS) {
        const int k  = s >> 4;
        const int sl = s & (LANES - 1);
        const int kr = k / 7, kc = k - kr * 7;
        const int c  = c0 + 2 * sl;
        float v0 = w7[c * 49 + k];
        float v1 = w7[(c + 1) * 49 + k];
        if (kr >= 1 && kr <= 5 && kc >= 1 && kc <= 5) {
            const int k5 = (kr - 1) * 5 + (kc - 1);
            v0 += w5[c * 25 + k5];
            v1 += w5[(c + 1) * 25 + k5];
        }
        if (kr >= 2 && kr <= 4 && kc >= 2 && kc <= 4) {
            const int k3 = (kr - 2) * 3 + (kc - 2);
            v0 += w3[c * 9 + k3];
            v1 += w3[(c + 1) * 9 + k3];
        }
        if (kr == 3 && kc == 3) { v0 += 1.0f; v1 += 1.0f; }
        s_w[sl * WP + kr * 8 + kc] = pack2(v0, v1);
    }

    // --- cls token pass-through ---
    if (blockIdx.y == 0 && tid < LANES) {
        const int off = (b * NTOK) * (DIM / 2) + (c0 >> 1) + tid;
        o64[off] = x64[off];
    }

    // --- Stage input tile (22x22 x 32ch), pos-major, zero-padded halo ---
    {
        const ull* xb = x64 + (size_t)tokbase * (DIM / 2) + cl;
        ull* sp = s_in + lane * SP;

        int col = pg;                  // 0..15 < TIN
        int gh  = h0 - 3;
        int off = gh * WGRID + (w0 - 3 + col);

        #pragma unroll 4
        for (int p = pg; p < SPOS; p += 16) {
            const int gw = w0 - 3 + col;
            ull v = 0ull;
            if ((unsigned)gh < (unsigned)HGRID && (unsigned)gw < (unsigned)WGRID)
                v = xb[(long)off * (DIM / 2)];
            sp[p] = v;
            col += 16; off += 16;
            if (col >= TIN) { col -= TIN; gh++; off += WGRID - TIN; }
        }
    }

    // --- Bias ---
    const int cb = c0 + 2 * lane;
    const float bias0 = b7[cb] + b5[cb] + b3[cb];
    const float bias1 = b7[cb + 1] + b5[cb + 1] + b3[cb + 1];

    __syncthreads();

    // --- Each thread: 2 rows x 8 cols, 2 channels (scalar FFMA math) ---
    const int y   = tid >> 4;           // 0..15
    const int rp  = y & 7;              // row pair 0..7
    const int q0  = (y >> 3) * 8;       // col half: 0 or 8
    const int or0 = 2 * rp;

    const float* inb = (const float*)(s_in + lane * SP + q0);
    const float* wb  = (const float*)(s_w + lane * WP);

    float a0[16], a1[16];               // [2c+ch]
    #pragma unroll
    for (int c = 0; c < 8; ++c) {
        a0[2 * c] = bias0; a0[2 * c + 1] = bias1;
        a1[2 * c] = bias0; a1[2 * c + 1] = bias1;
    }

    float wbuf[2][16];                  // ping-pong weight rows [kc*2+ch]

    #pragma unroll
    for (int ir = 0; ir < 8; ++ir) {    // input rows or0 .. or0+7
        float in[28];                   // 14 positions x 2 channels
        {
            const float4* ip = (const float4*)(inb + (or0 + ir) * TIN * 2);
            #pragma unroll
            for (int j = 0; j < 7; ++j) {
                float4 v = ip[j];
                in[4 * j]     = v.x; in[4 * j + 1] = v.y;
                in[4 * j + 2] = v.z; in[4 * j + 3] = v.w;
            }
        }

        if (ir <= 6) {                  // load weight row ir, feed a0
            float* wcur = wbuf[ir & 1];
            const float4* wp4 = (const float4*)(wb + ir * 16);
            #pragma unroll
            for (int j = 0; j < 4; ++j) {
                float4 v = wp4[j];
                wcur[4 * j]     = v.x; wcur[4 * j + 1] = v.y;
                wcur[4 * j + 2] = v.z; wcur[4 * j + 3] = v.w;
            }
            #pragma unroll
            for (int kc = 0; kc < 7; ++kc)
                #pragma unroll
                for (int c = 0; c < 8; ++c) {
                    a0[2 * c]     = fmaf(in[2 * (c + kc)],     wcur[2 * kc],     a0[2 * c]);
                    a0[2 * c + 1] = fmaf(in[2 * (c + kc) + 1], wcur[2 * kc + 1], a0[2 * c + 1]);
                }
        }
        if (ir >= 1) {                  // weight row ir-1 already resident
            const float* wprev = wbuf[(ir - 1) & 1];
            #pragma unroll
            for (int kc = 0; kc < 7; ++kc)
                #pragma unroll
                for (int c = 0; c < 8; ++c) {
                    a1[2 * c]     = fmaf(in[2 * (c + kc)],     wprev[2 * kc],     a1[2 * c]);
                    a1[2 * c + 1] = fmaf(in[2 * (c + kc) + 1], wprev[2 * kc + 1], a1[2 * c + 1]);
                }
        }
    }

    // --- Store 2 rows x 8 cols (64-bit packed stores) ---
    const int row0 = (tokbase + (h0 + or0) * WGRID + (w0 + q0)) * (DIM / 2) + cl;
    const int row1 = row0 + WGRID * (DIM / 2);
    #pragma unroll
    for (int c = 0; c < 8; ++c) {
        o64[row0 + c * (DIM / 2)] = pack2(a0[2 * c], a0[2 * c + 1]);
        o64[row1 + c * (DIM / 2)] = pack2(a1[2 * c], a1[2 * c + 1]);
    }
}

// ---------------------------------------------------------------------------
extern "C" void kernel_launch(void* const* d_in, const int* in_sizes, int n_in,
                              void* d_out, int out_size) {
    const float* x  = (const float*)d_in[0];
    const float* w7 = (const float*)d_in[1];
    const float* b7 = (const float*)d_in[2];
    const float* w5 = (const float*)d_in[3];
    const float* b5 = (const float*)d_in[4];
    const float* w3 = (const float*)d_in[5];
    const float* b3 = (const float*)d_in[6];
    float* out = (float*)d_out;

    cudaFuncSetAttribute(conv_kernel,
                         cudaFuncAttributeMaxDynamicSharedMemorySize, SMEM_BYTES);

    dim3 grid(DIM / CT, (HGRID / TILE) * (WGRID / TILE), BATCH);  // 16,16,16
    conv_kernel<<<grid, THREADS, SMEM_BYTES>>>(x, w7, b7, w5, b5, w3, b3, out);
}

// round 10
// speedup vs baseline: 1.2758x; 1.1362x over previous
#include <cuda_runtime.h>
#include <cuda_bf16.h>
#include <cstdint>

// Problem constants
#define BATCH 16
#define HGRID 64
#define WGRID 64
#define DIM   512
#define NTOK  (1 + HGRID * WGRID)     // 4097

// Tiling: 16x16 spatial tile, 32 channels (16 ull lanes)
#define CT        32
#define LANES     16
#define TILE      16
#define TIN       22                  // TILE + 6 halo
#define SPOS      (TIN * TIN)         // 484
#define SP        486                 // lane stride (ull): 486*8 mod 128 = 48 -> conflict-free
#define WP        58                  // weight lane stride: 58*8 mod 128 = 80 -> conflict-free
#define NW        49
#define THREADS   256

#define SMEM_ULL   (LANES * SP + LANES * WP)      // 7776 + 928 = 8704
#define SMEM_BYTES (SMEM_ULL * 8)                 // 69632

typedef unsigned long long ull;

__device__ __forceinline__ ull pack2(float lo, float hi) {
    ull d;
    asm("mov.b64 %0, {%1, %2};" : "=l"(d) : "f"(lo), "f"(hi));
    return d;
}

// Async 8-byte global->shared copy with zero-fill (src_size 0 or 8).
__device__ __forceinline__ void cp_async8(uint32_t dst_smem, const void* src,
                                          int src_size) {
    asm volatile("cp.async.ca.shared.global [%0], [%1], 8, %2;"
                 :: "r"(dst_smem), "l"(src), "r"(src_size));
}

// ---------------------------------------------------------------------------
// Single fused kernel: weight fusion + cls copy + 7x7 depthwise conv.
// Input tile staged via cp.async (no per-element scoreboard stall); weight
// fusion / cls / bias LDGs execute under the async flight.
// grid: (16 channel groups, 4x4 spatial tiles, 16 batch), 256 threads.
// ---------------------------------------------------------------------------
__global__ void __launch_bounds__(THREADS, 3)
conv_kernel(const float* __restrict__ x,
            const float* __restrict__ w7, const float* __restrict__ b7,
            const float* __restrict__ w5, const float* __restrict__ b5,
            const float* __restrict__ w3, const float* __restrict__ b3,
            float* __restrict__ out) {
    extern __shared__ ull sm[];
    ull* s_in = sm;                    // [LANES][SP]  pos-major per lane
    ull* s_w  = sm + LANES * SP;       // [LANES][WP]  8 slots per kr row

    const int tid  = threadIdx.x;
    const int lane = tid & (LANES - 1);
    const int pg   = tid >> 4;                     // 0..15

    const int c0 = blockIdx.x * CT;
    const int h0 = (blockIdx.y >> 2) * TILE;
    const int w0 = (blockIdx.y & 3) * TILE;
    const int b  = blockIdx.z;

    const ull* x64 = (const ull*)x;
    ull* o64       = (ull*)out;
    const int cl      = (c0 >> 1) + lane;
    const int tokbase = b * NTOK + 1;              // skip cls token

    // --- 1) Issue ALL input-tile cp.asyncs first (fire-and-forget) ---
    {
        const ull* xb = x64 + (size_t)tokbase * (DIM / 2) + cl;
        uint32_t sdst =
            (uint32_t)__cvta_generic_to_shared(s_in + lane * SP);

        int col = pg;                  // 0..15 < TIN
        int gh  = h0 - 3;
        int off = gh * WGRID + (w0 - 3 + col);

        #pragma unroll 4
        for (int p = pg; p < SPOS; p += 16) {
            const int gw = w0 - 3 + col;
            const bool ok = ((unsigned)gh < (unsigned)HGRID) &&
                            ((unsigned)gw < (unsigned)WGRID);
            const long go = ok ? (long)off : 0;    // clamp OOB address
            cp_async8(sdst + (uint32_t)p * 8u,
                      xb + go * (DIM / 2), ok ? 8 : 0);
            col += 16; off += 16;
            if (col >= TIN) { col -= TIN; gh++; off += WGRID - TIN; }
        }
        asm volatile("cp.async.commit_group;" ::: "memory");
    }

    // --- 2) Weight fusion under async flight: w7+pad(w5)+pad(w3)+identity ---
    #pragma unroll 1
    for (int s = tid; s < NW * LANES; s += THREADS) {
        const int k  = s >> 4;
        const int sl = s & (LANES - 1);
        const int kr = k / 7, kc = k - kr * 7;
        const int c  = c0 + 2 * sl;
        float v0 = w7[c * 49 + k];
        float v1 = w7[(c + 1) * 49 + k];
        if (kr >= 1 && kr <= 5 && kc >= 1 && kc <= 5) {
            const int k5 = (kr - 1) * 5 + (kc - 1);
            v0 += w5[c * 25 + k5];
            v1 += w5[(c + 1) * 25 + k5];
        }
        if (kr >= 2 && kr <= 4 && kc >= 2 && kc <= 4) {
            const int k3 = (kr - 2) * 3 + (kc - 2);
            v0 += w3[c * 9 + k3];
            v1 += w3[(c + 1) * 9 + k3];
        }
        if (kr == 3 && kc == 3) { v0 += 1.0f; v1 += 1.0f; }
        s_w[sl * WP + kr * 8 + kc] = pack2(v0, v1);
    }

    // --- 3) cls token pass-through (also under flight) ---
    if (blockIdx.y == 0 && tid < LANES) {
        const int off = (b * NTOK) * (DIM / 2) + (c0 >> 1) + tid;
        o64[off] = x64[off];
    }

    // --- 4) Bias (under flight) ---
    const int cb = c0 + 2 * lane;
    const float bias0 = b7[cb] + b5[cb] + b3[cb];
    const float bias1 = b7[cb + 1] + b5[cb + 1] + b3[cb + 1];

    // --- 5) Drain async copies, then block barrier ---
    asm volatile("cp.async.wait_group 0;" ::: "memory");
    __syncthreads();

    // --- Each thread: 2 rows x 8 cols, 2 channels (scalar FFMA math) ---
    const int y   = tid >> 4;           // 0..15
    const int rp  = y & 7;              // row pair 0..7
    const int q0  = (y >> 3) * 8;       // col half: 0 or 8
    const int or0 = 2 * rp;

    const float* inb = (const float*)(s_in + lane * SP + q0);
    const float* wb  = (const float*)(s_w + lane * WP);

    float a0[16], a1[16];               // [2c+ch]
    #pragma unroll
    for (int c = 0; c < 8; ++c) {
        a0[2 * c] = bias0; a0[2 * c + 1] = bias1;
        a1[2 * c] = bias0; a1[2 * c + 1] = bias1;
    }

    float wbuf[2][16];                  // ping-pong weight rows [kc*2+ch]

    #pragma unroll
    for (int ir = 0; ir < 8; ++ir) {    // input rows or0 .. or0+7
        float in[28];                   // 14 positions x 2 channels
        {
            const float4* ip = (const float4*)(inb + (or0 + ir) * TIN * 2);
            #pragma unroll
            for (int j = 0; j < 7; ++j) {
                float4 v = ip[j];
                in[4 * j]     = v.x; in[4 * j + 1] = v.y;
                in[4 * j + 2] = v.z; in[4 * j + 3] = v.w;
            }
        }

        if (ir <= 6) {                  // load weight row ir, feed a0
            float* wcur = wbuf[ir & 1];
            const float4* wp4 = (const float4*)(wb + ir * 16);
            #pragma unroll
            for (int j = 0; j < 4; ++j) {
                float4 v = wp4[j];
                wcur[4 * j]     = v.x; wcur[4 * j + 1] = v.y;
                wcur[4 * j + 2] = v.z; wcur[4 * j + 3] = v.w;
            }
            #pragma unroll
            for (int kc = 0; kc < 7; ++kc)
                #pragma unroll
                for (int c = 0; c < 8; ++c) {
                    a0[2 * c]     = fmaf(in[2 * (c + kc)],     wcur[2 * kc],     a0[2 * c]);
                    a0[2 * c + 1] = fmaf(in[2 * (c + kc) + 1], wcur[2 * kc + 1], a0[2 * c + 1]);
                }
        }
        if (ir >= 1) {                  // weight row ir-1 already resident
            const float* wprev = wbuf[(ir - 1) & 1];
            #pragma unroll
            for (int kc = 0; kc < 7; ++kc)
                #pragma unroll
                for (int c = 0; c < 8; ++c) {
                    a1[2 * c]     = fmaf(in[2 * (c + kc)],     wprev[2 * kc],     a1[2 * c]);
                    a1[2 * c + 1] = fmaf(in[2 * (c + kc) + 1], wprev[2 * kc + 1], a1[2 * c + 1]);
                }
        }
    }

    // --- Store 2 rows x 8 cols (64-bit packed stores) ---
    const int row0 = (tokbase + (h0 + or0) * WGRID + (w0 + q0)) * (DIM / 2) + cl;
    const int row1 = row0 + WGRID * (DIM / 2);
    #pragma unroll
    for (int c = 0; c < 8; ++c) {
        o64[row0 + c * (DIM / 2)] = pack2(a0[2 * c], a0[2 * c + 1]);
        o64[row1 + c * (DIM / 2)] = pack2(a1[2 * c], a1[2 * c + 1]);
    }
}

// ---------------------------------------------------------------------------
extern "C" void kernel_launch(void* const* d_in, const int* in_sizes, int n_in,
                              void* d_out, int out_size) {
    const float* x  = (const float*)d_in[0];
    const float* w7 = (const float*)d_in[1];
    const float* b7 = (const float*)d_in[2];
    const float* w5 = (const float*)d_in[3];
    const float* b5 = (const float*)d_in[4];
    const float* w3 = (const float*)d_in[5];
    const float* b3 = (const float*)d_in[6];
    float* out = (float*)d_out;

    cudaFuncSetAttribute(conv_kernel,
                         cudaFuncAttributeMaxDynamicSharedMemorySize, SMEM_BYTES);

    dim3 grid(DIM / CT, (HGRID / TILE) * (WGRID / TILE), BATCH);  // 16,16,16
    conv_kernel<<<grid, THREADS, SMEM_BYTES>>>(x, w7, b7, w5, b5, w3, b3, out);
}

// round 11
// speedup vs baseline: 1.4136x; 1.1080x over previous
#include <cuda_runtime.h>
#include <cuda_bf16.h>
#include <cstdint>

// Problem constants
#define BATCH 16
#define HGRID 64
#define WGRID 64
#define DIM   512
#define NTOK  (1 + HGRID * WGRID)     // 4097

// Tiling: 16x16 spatial tile, 32 channels (16 ull lanes)
#define CT        32
#define LANES     16
#define TILE      16
#define TIN       22                  // TILE + 6 halo
#define SPOS      (TIN * TIN)         // 484
#define SP        486                 // lane stride (ull): 486*8 mod 128 = 48 -> conflict-free
#define WP        58                  // weight lane stride: 58*8 mod 128 = 80 -> conflict-free
#define NW        49
#define THREADS   256

#define SMEM_ULL   (LANES * SP + LANES * WP)      // 7776 + 928 = 8704
#define SMEM_BYTES (SMEM_ULL * 8)                 // 69632

typedef unsigned long long ull;

__device__ __forceinline__ ull fma2(ull a, ull b, ull c) {
    ull d;
    asm("fma.rn.f32x2 %0, %1, %2, %3;" : "=l"(d) : "l"(a), "l"(b), "l"(c));
    return d;
}

__device__ __forceinline__ ull pack2(float lo, float hi) {
    ull d;
    asm("mov.b64 %0, {%1, %2};" : "=l"(d) : "f"(lo), "f"(hi));
    return d;
}

// Async 8-byte global->shared copy with zero-fill (src_size 0 or 8).
__device__ __forceinline__ void cp_async8(uint32_t dst_smem, const void* src,
                                          int src_size) {
    asm volatile("cp.async.ca.shared.global [%0], [%1], 8, %2;"
                 :: "r"(dst_smem), "l"(src), "r"(src_size));
}

// ---------------------------------------------------------------------------
// Single fused kernel: weight fusion + cls copy + 7x7 depthwise conv.
// cp.async staging (R10) + packed f32x2 math (halves FFMA instruction count).
// grid: (16 channel groups, 4x4 spatial tiles, 16 batch), 256 threads.
// ---------------------------------------------------------------------------
__global__ void __launch_bounds__(THREADS, 3)
conv_kernel(const float* __restrict__ x,
            const float* __restrict__ w7, const float* __restrict__ b7,
            const float* __restrict__ w5, const float* __restrict__ b5,
            const float* __restrict__ w3, const float* __restrict__ b3,
            float* __restrict__ out) {
    extern __shared__ ull sm[];
    ull* s_in = sm;                    // [LANES][SP]  pos-major per lane
    ull* s_w  = sm + LANES * SP;       // [LANES][WP]  8 slots per kr row

    const int tid  = threadIdx.x;
    const int lane = tid & (LANES - 1);
    const int pg   = tid >> 4;                     // 0..15

    const int c0 = blockIdx.x * CT;
    const int h0 = (blockIdx.y >> 2) * TILE;
    const int w0 = (blockIdx.y & 3) * TILE;
    const int b  = blockIdx.z;

    const ull* x64 = (const ull*)x;
    ull* o64       = (ull*)out;
    const int cl      = (c0 >> 1) + lane;
    const int tokbase = b * NTOK + 1;              // skip cls token

    // --- 1) Issue ALL input-tile cp.asyncs first (fire-and-forget) ---
    {
        const ull* xb = x64 + (size_t)tokbase * (DIM / 2) + cl;
        uint32_t sdst =
            (uint32_t)__cvta_generic_to_shared(s_in + lane * SP);

        int col = pg;                  // 0..15 < TIN
        int gh  = h0 - 3;
        int off = gh * WGRID + (w0 - 3 + col);

        #pragma unroll 4
        for (int p = pg; p < SPOS; p += 16) {
            const int gw = w0 - 3 + col;
            const bool ok = ((unsigned)gh < (unsigned)HGRID) &&
                            ((unsigned)gw < (unsigned)WGRID);
            const long go = ok ? (long)off : 0;    // clamp OOB address
            cp_async8(sdst + (uint32_t)p * 8u,
                      xb + go * (DIM / 2), ok ? 8 : 0);
            col += 16; off += 16;
            if (col >= TIN) { col -= TIN; gh++; off += WGRID - TIN; }
        }
        asm volatile("cp.async.commit_group;" ::: "memory");
    }

    // --- 2) Weight fusion under async flight: w7+pad(w5)+pad(w3)+identity ---
    #pragma unroll 1
    for (int s = tid; s < NW * LANES; s += THREADS) {
        const int k  = s >> 4;
        const int sl = s & (LANES - 1);
        const int kr = k / 7, kc = k - kr * 7;
        const int c  = c0 + 2 * sl;
        float v0 = w7[c * 49 + k];
        float v1 = w7[(c + 1) * 49 + k];
        if (kr >= 1 && kr <= 5 && kc >= 1 && kc <= 5) {
            const int k5 = (kr - 1) * 5 + (kc - 1);
            v0 += w5[c * 25 + k5];
            v1 += w5[(c + 1) * 25 + k5];
        }
        if (kr >= 2 && kr <= 4 && kc >= 2 && kc <= 4) {
            const int k3 = (kr - 2) * 3 + (kc - 2);
            v0 += w3[c * 9 + k3];
            v1 += w3[(c + 1) * 9 + k3];
        }
        if (kr == 3 && kc == 3) { v0 += 1.0f; v1 += 1.0f; }
        s_w[sl * WP + kr * 8 + kc] = pack2(v0, v1);
    }

    // --- 3) cls token pass-through (also under flight) ---
    if (blockIdx.y == 0 && tid < LANES) {
        const int off = (b * NTOK) * (DIM / 2) + (c0 >> 1) + tid;
        o64[off] = x64[off];
    }

    // --- 4) Bias (under flight) ---
    const int cb = c0 + 2 * lane;
    const ull bv = pack2(b7[cb] + b5[cb] + b3[cb],
                         b7[cb + 1] + b5[cb + 1] + b3[cb + 1]);

    // --- 5) Drain async copies, then block barrier ---
    asm volatile("cp.async.wait_group 0;" ::: "memory");
    __syncthreads();

    // --- Each thread: 2 rows x 8 cols, 2 channels (packed f32x2 math) ---
    const int y   = tid >> 4;           // 0..15
    const int rp  = y & 7;              // row pair 0..7
    const int q0  = (y >> 3) * 8;       // col half: 0 or 8
    const int or0 = 2 * rp;

    const ull* inb = s_in + lane * SP + q0;
    const ull* wb  = s_w + lane * WP;

    ull a0[8], a1[8];
    #pragma unroll
    for (int c = 0; c < 8; ++c) { a0[c] = bv; a1[c] = bv; }

    ull wbuf[2][8];                     // ping-pong weight rows

    #pragma unroll
    for (int ir = 0; ir < 8; ++ir) {    // input rows or0 .. or0+7
        ull in[14];
        {
            const ulonglong2* ip = (const ulonglong2*)(inb + (or0 + ir) * TIN);
            #pragma unroll
            for (int j = 0; j < 7; ++j) {
                ulonglong2 v = ip[j];
                in[2 * j]     = v.x;
                in[2 * j + 1] = v.y;
            }
        }

        if (ir <= 6) {                  // load weight row ir, feed a0
            const ulonglong2* wp2 = (const ulonglong2*)(wb + ir * 8);
            #pragma unroll
            for (int j = 0; j < 4; ++j) {
                ulonglong2 v = wp2[j];
                wbuf[ir & 1][2 * j]     = v.x;
                wbuf[ir & 1][2 * j + 1] = v.y;
            }
            #pragma unroll
            for (int kc = 0; kc < 7; ++kc)
                #pragma unroll
                for (int c = 0; c < 8; ++c)
                    a0[c] = fma2(in[c + kc], wbuf[ir & 1][kc], a0[c]);
        }
        if (ir >= 1) {                  // weight row ir-1 already resident
            #pragma unroll
            for (int kc = 0; kc < 7; ++kc)
                #pragma unroll
                for (int c = 0; c < 8; ++c)
                    a1[c] = fma2(in[c + kc], wbuf[(ir - 1) & 1][kc], a1[c]);
        }
    }

    // --- Store 2 rows x 8 cols ---
    const int row0 = (tokbase + (h0 + or0) * WGRID + (w0 + q0)) * (DIM / 2) + cl;
    const int row1 = row0 + WGRID * (DIM / 2);
    #pragma unroll
    for (int c = 0; c < 8; ++c) {
        o64[row0 + c * (DIM / 2)] = a0[c];
        o64[row1 + c * (DIM / 2)] = a1[c];
    }
}

// ---------------------------------------------------------------------------
extern "C" void kernel_launch(void* const* d_in, const int* in_sizes, int n_in,
                              void* d_out, int out_size) {
    const float* x  = (const float*)d_in[0];
    const float* w7 = (const float*)d_in[1];
    const float* b7 = (const float*)d_in[2];
    const float* w5 = (const float*)d_in[3];
    const float* b5 = (const float*)d_in[4];
    const float* w3 = (const float*)d_in[5];
    const float* b3 = (const float*)d_in[6];
    float* out = (float*)d_out;

    cudaFuncSetAttribute(conv_kernel,
                         cudaFuncAttributeMaxDynamicSharedMemorySize, SMEM_BYTES);

    dim3 grid(DIM / CT, (HGRID / TILE) * (WGRID / TILE), BATCH);  // 16,16,16
    conv_kernel<<<grid, THREADS, SMEM_BYTES>>>(x, w7, b7, w5, b5, w3, b3, out);
}

// round 12
// speedup vs baseline: 1.5050x; 1.0647x over previous
#include <cuda_runtime.h>
#include <cuda_bf16.h>
#include <cstdint>

// Problem constants
#define BATCH 16
#define HGRID 64
#define WGRID 64
#define DIM   512
#define NTOK  (1 + HGRID * WGRID)     // 4097

// Tiling: 32 rows x 16 cols spatial tile, 32 channels (16 ull lanes)
#define CT        32
#define LANES     16
#define TILE_H    32
#define TILE_W    16
#define TINH      (TILE_H + 6)        // 38
#define TINW      (TILE_W + 6)        // 22
#define SPOS      (TINH * TINW)       // 836
#define SP        838                 // lane stride (ull): 838*8 mod 128 = 48 -> conflict-free
#define WP        58                  // weight lane stride: 58*8 mod 128 = 80 -> conflict-free
#define NW        49
#define THREADS   256

#define SMEM_ULL   (LANES * SP + LANES * WP)      // 13408 + 928 = 14336
#define SMEM_BYTES (SMEM_ULL * 8)                 // 114688 (x2 blocks = 229376 <= 233472)

typedef unsigned long long ull;

__device__ __forceinline__ ull fma2(ull a, ull b, ull c) {
    ull d;
    asm("fma.rn.f32x2 %0, %1, %2, %3;" : "=l"(d) : "l"(a), "l"(b), "l"(c));
    return d;
}

__device__ __forceinline__ ull pack2(float lo, float hi) {
    ull d;
    asm("mov.b64 %0, {%1, %2};" : "=l"(d) : "f"(lo), "f"(hi));
    return d;
}

// Async 8-byte global->shared copy with zero-fill (src_size 0 or 8).
__device__ __forceinline__ void cp_async8(uint32_t dst_smem, const void* src,
                                          int src_size) {
    asm volatile("cp.async.ca.shared.global [%0], [%1], 8, %2;"
                 :: "r"(dst_smem), "l"(src), "r"(src_size));
}

// ---------------------------------------------------------------------------
// Single fused kernel: weight fusion + cls copy + 7x7 depthwise conv.
// cp.async staging + packed f32x2 math. Each thread: 2 rows x 16 cols x 2ch
// (full tile width) -> each input row LDS'd once per thread, -31% crossbar.
// Single weight-row buffer: a1 consumes old row, then reload, then a0.
// grid: (16 channel groups, 2x4 spatial tiles, 16 batch), 256 threads.
// ---------------------------------------------------------------------------
__global__ void __launch_bounds__(THREADS, 2)
conv_kernel(const float* __restrict__ x,
            const float* __restrict__ w7, const float* __restrict__ b7,
            const float* __restrict__ w5, const float* __restrict__ b5,
            const float* __restrict__ w3, const float* __restrict__ b3,
            float* __restrict__ out) {
    extern __shared__ ull sm[];
    ull* s_in = sm;                    // [LANES][SP]  pos-major per lane
    ull* s_w  = sm + LANES * SP;       // [LANES][WP]  8 slots per kr row

    const int tid  = threadIdx.x;
    const int lane = tid & (LANES - 1);
    const int pg   = tid >> 4;                     // 0..15

    const int c0 = blockIdx.x * CT;
    const int h0 = (blockIdx.y >> 2) * TILE_H;
    const int w0 = (blockIdx.y & 3) * TILE_W;
    const int b  = blockIdx.z;

    const ull* x64 = (const ull*)x;
    ull* o64       = (ull*)out;
    const int cl      = (c0 >> 1) + lane;
    const int tokbase = b * NTOK + 1;              // skip cls token

    // --- 1) Issue ALL input-tile cp.asyncs first (fire-and-forget) ---
    {
        const ull* xb = x64 + (size_t)tokbase * (DIM / 2) + cl;
        uint32_t sdst =
            (uint32_t)__cvta_generic_to_shared(s_in + lane * SP);

        int col = pg;                  // 0..15 < TINW
        int gh  = h0 - 3;
        int off = gh * WGRID + (w0 - 3 + col);

        #pragma unroll 4
        for (int p = pg; p < SPOS; p += 16) {
            const int gw = w0 - 3 + col;
            const bool ok = ((unsigned)gh < (unsigned)HGRID) &&
                            ((unsigned)gw < (unsigned)WGRID);
            const long go = ok ? (long)off : 0;    // clamp OOB address
            cp_async8(sdst + (uint32_t)p * 8u,
                      xb + go * (DIM / 2), ok ? 8 : 0);
            col += 16; off += 16;
            if (col >= TINW) { col -= TINW; gh++; off += WGRID - TINW; }
        }
        asm volatile("cp.async.commit_group;" ::: "memory");
    }

    // --- 2) Weight fusion under async flight: w7+pad(w5)+pad(w3)+identity ---
    #pragma unroll 1
    for (int s = tid; s < NW * LANES; s += THREADS) {
        const int k  = s >> 4;
        const int sl = s & (LANES - 1);
        const int kr = k / 7, kc = k - kr * 7;
        const int c  = c0 + 2 * sl;
        float v0 = w7[c * 49 + k];
        float v1 = w7[(c + 1) * 49 + k];
        if (kr >= 1 && kr <= 5 && kc >= 1 && kc <= 5) {
            const int k5 = (kr - 1) * 5 + (kc - 1);
            v0 += w5[c * 25 + k5];
            v1 += w5[(c + 1) * 25 + k5];
        }
        if (kr >= 2 && kr <= 4 && kc >= 2 && kc <= 4) {
            const int k3 = (kr - 2) * 3 + (kc - 2);
            v0 += w3[c * 9 + k3];
            v1 += w3[(c + 1) * 9 + k3];
        }
        if (kr == 3 && kc == 3) { v0 += 1.0f; v1 += 1.0f; }
        s_w[sl * WP + kr * 8 + kc] = pack2(v0, v1);
    }

    // --- 3) cls token pass-through (under flight) ---
    if (blockIdx.y == 0 && tid < LANES) {
        const int off = (b * NTOK) * (DIM / 2) + (c0 >> 1) + tid;
        o64[off] = x64[off];
    }

    // --- 4) Bias (under flight) ---
    const int cb = c0 + 2 * lane;
    const ull bv = pack2(b7[cb] + b5[cb] + b3[cb],
                         b7[cb + 1] + b5[cb + 1] + b3[cb + 1]);

    // --- 5) Drain async copies, then block barrier ---
    asm volatile("cp.async.wait_group 0;" ::: "memory");
    __syncthreads();

    // --- Each thread: 2 rows x 16 cols, 2 channels (packed f32x2 math) ---
    const int y   = tid >> 4;           // 0..15 = row pair
    const int or0 = 2 * y;

    const ull* inb = s_in + lane * SP;
    const ull* wb  = s_w + lane * WP;

    ull a0[16], a1[16];
    #pragma unroll
    for (int c = 0; c < 16; ++c) { a0[c] = bv; a1[c] = bv; }

    ull wbuf[8];                        // single weight-row buffer

    #pragma unroll
    for (int ir = 0; ir < 8; ++ir) {    // input rows or0 .. or0+7
        ull in[22];
        {
            const ulonglong2* ip = (const ulonglong2*)(inb + (or0 + ir) * TINW);
            #pragma unroll
            for (int j = 0; j < 11; ++j) {
                ulonglong2 v = ip[j];
                in[2 * j]     = v.x;
                in[2 * j + 1] = v.y;
            }
        }

        // a1 consumes wbuf (= weight row ir-1) before it is overwritten
        if (ir >= 1) {
            #pragma unroll
            for (int kc = 0; kc < 7; ++kc)
                #pragma unroll
                for (int c = 0; c < 16; ++c)
                    a1[c] = fma2(in[c + kc], wbuf[kc], a1[c]);
        }
        // reload wbuf with weight row ir, then feed a0
        if (ir <= 6) {
            const ulonglong2* wp2 = (const ulonglong2*)(wb + ir * 8);
            #pragma unroll
            for (int j = 0; j < 4; ++j) {
                ulonglong2 v = wp2[j];
                wbuf[2 * j]     = v.x;
                wbuf[2 * j + 1] = v.y;
            }
            #pragma unroll
            for (int kc = 0; kc < 7; ++kc)
                #pragma unroll
                for (int c = 0; c < 16; ++c)
                    a0[c] = fma2(in[c + kc], wbuf[kc], a0[c]);
        }
    }

    // --- Store 2 rows x 16 cols ---
    const int row0 = (tokbase + (h0 + or0) * WGRID + w0) * (DIM / 2) + cl;
    const int row1 = row0 + WGRID * (DIM / 2);
    #pragma unroll
    for (int c = 0; c < 16; ++c) {
        o64[row0 + c * (DIM / 2)] = a0[c];
        o64[row1 + c * (DIM / 2)] = a1[c];
    }
}

// ---------------------------------------------------------------------------
extern "C" void kernel_launch(void* const* d_in, const int* in_sizes, int n_in,
                              void* d_out, int out_size) {
    const float* x  = (const float*)d_in[0];
    const float* w7 = (const float*)d_in[1];
    const float* b7 = (const float*)d_in[2];
    const float* w5 = (const float*)d_in[3];
    const float* b5 = (const float*)d_in[4];
    const float* w3 = (const float*)d_in[5];
    const float* b3 = (const float*)d_in[6];
    float* out = (float*)d_out;

    cudaFuncSetAttribute(conv_kernel,
                         cudaFuncAttributeMaxDynamicSharedMemorySize, SMEM_BYTES);

    dim3 grid(DIM / CT, (HGRID / TILE_H) * (WGRID / TILE_W), BATCH);  // 16,8,16
    conv_kernel<<<grid, THREADS, SMEM_BYTES>>>(x, w7, b7, w5, b5, w3, b3, out);
}

// round 13
// speedup vs baseline: 1.6348x; 1.0862x over previous
#include <cuda_runtime.h>
#include <cuda_bf16.h>
#include <cstdint>

// Problem constants
#define BATCH 16
#define HGRID 64
#define WGRID 64
#define DIM   512
#define NTOK  (1 + HGRID * WGRID)     // 4097

// Tiling: 32 rows x 16 cols spatial tile, 32 channels (16 ull lanes)
#define CT        32
#define LANES     16
#define TILE_H    32
#define TILE_W    16
#define TINH      (TILE_H + 6)        // 38
#define TINW      (TILE_W + 6)        // 22
#define SPOS      (TINH * TINW)       // 836
#define SP        838                 // lane stride (ull): 838*8 mod 128 = 48 -> conflict-free
#define WP        58                  // weight lane stride (>=56), 58*8 mod 128 = 80 -> conflict-free
#define NSLOT     56                  // 7 kr rows x 8 padded kc slots
#define THREADS   256

#define SMEM_ULL   (LANES * SP + LANES * WP)      // 13408 + 928 = 14336
#define SMEM_BYTES (SMEM_ULL * 8)                 // 114688 (x2 blocks = 229376)

typedef unsigned long long ull;

// One-time fused weights [slot][cl] (slot = kr*8+kc, cl = channel-pair) + bias
__device__ __align__(16) ull g_wf[NSLOT * (DIM / 2)];
__device__ __align__(16) ull g_bs[DIM / 2];

__device__ __forceinline__ ull fma2(ull a, ull b, ull c) {
    ull d;
    asm("fma.rn.f32x2 %0, %1, %2, %3;" : "=l"(d) : "l"(a), "l"(b), "l"(c));
    return d;
}

__device__ __forceinline__ ull pack2(float lo, float hi) {
    ull d;
    asm("mov.b64 %0, {%1, %2};" : "=l"(d) : "f"(lo), "f"(hi));
    return d;
}

// Async 8-byte global->shared copy with zero-fill (src_size 0 or 8).
__device__ __forceinline__ void cp_async8(uint32_t dst_smem, const void* src,
                                          int src_size) {
    asm volatile("cp.async.ca.shared.global [%0], [%1], 8, %2;"
                 :: "r"(dst_smem), "l"(src), "r"(src_size));
}

// ---------------------------------------------------------------------------
// Prep: fuse w7+pad(w5)+pad(w3)+identity -> g_wf (padded slot layout, packed
// channel pairs), sum biases -> g_bs, and cls-token pass-through.
// ---------------------------------------------------------------------------
#define PREP_WF  (NSLOT * (DIM / 2))              // 14336
#define PREP_BS  (DIM / 2)                        // 256
#define PREP_CLS (BATCH * (DIM / 2))              // 4096
#define PREP_TOT (PREP_WF + PREP_BS + PREP_CLS)   // 18688

__global__ void prep_kernel(const float* __restrict__ x,
                            const float* __restrict__ w7, const float* __restrict__ b7,
                            const float* __restrict__ w5, const float* __restrict__ b5,
                            const float* __restrict__ w3, const float* __restrict__ b3,
                            float* __restrict__ out) {
    const int idx = blockIdx.x * blockDim.x + threadIdx.x;
    if (idx < PREP_WF) {
        const int slot = idx >> 8;                 // 0..55
        const int cl   = idx & 255;
        const int kr = slot >> 3, kc = slot & 7;
        ull v = 0ull;
        if (kc < 7) {                              // kc==7 is padding
            const int c = 2 * cl;
            const int k = kr * 7 + kc;
            float v0 = w7[c * 49 + k];
            float v1 = w7[(c + 1) * 49 + k];
            if (kr >= 1 && kr <= 5 && kc >= 1 && kc <= 5) {
                const int k5 = (kr - 1) * 5 + (kc - 1);
                v0 += w5[c * 25 + k5];
                v1 += w5[(c + 1) * 25 + k5];
            }
            if (kr >= 2 && kr <= 4 && kc >= 2 && kc <= 4) {
                const int k3 = (kr - 2) * 3 + (kc - 2);
                v0 += w3[c * 9 + k3];
                v1 += w3[(c + 1) * 9 + k3];
            }
            if (kr == 3 && kc == 3) { v0 += 1.0f; v1 += 1.0f; }
            v = pack2(v0, v1);
        }
        g_wf[idx] = v;
    } else if (idx < PREP_WF + PREP_BS) {
        const int cl = idx - PREP_WF;
        const int c  = 2 * cl;
        g_bs[cl] = pack2(b7[c] + b5[c] + b3[c],
                         b7[c + 1] + b5[c + 1] + b3[c + 1]);
    } else if (idx < PREP_TOT) {
        const int i  = idx - PREP_WF - PREP_BS;
        const int b  = i >> 8;
        const int cl = i & 255;
        const size_t off = (size_t)b * NTOK * (DIM / 2) + cl;
        ((ull*)out)[off] = ((const ull*)x)[off];
    }
}

// ---------------------------------------------------------------------------
// Conv: cp.async staging (input tile + prefused weights) + f32x2 math.
// Each thread: 2 rows x 16 cols x 2 channels (full tile width).
// grid: (16 channel groups, 2x4 spatial tiles, 16 batch), 256 threads.
// ---------------------------------------------------------------------------
__global__ void __launch_bounds__(THREADS, 2)
conv_kernel(const float* __restrict__ x, float* __restrict__ out) {
    extern __shared__ ull sm[];
    ull* s_in = sm;                    // [LANES][SP]  pos-major per lane
    ull* s_w  = sm + LANES * SP;       // [LANES][WP]  slot-indexed per lane

    const int tid  = threadIdx.x;
    const int lane = tid & (LANES - 1);
    const int pg   = tid >> 4;                     // 0..15

    const int c0 = blockIdx.x * CT;
    const int h0 = (blockIdx.y >> 2) * TILE_H;
    const int w0 = (blockIdx.y & 3) * TILE_W;
    const int b  = blockIdx.z;

    const ull* x64 = (const ull*)x;
    ull* o64       = (ull*)out;
    const int cl      = (c0 >> 1) + lane;
    const int tokbase = b * NTOK + 1;              // skip cls token

    // --- 1) Input tile cp.asyncs (fire-and-forget) ---
    {
        const ull* xb = x64 + (size_t)tokbase * (DIM / 2) + cl;
        uint32_t sdst =
            (uint32_t)__cvta_generic_to_shared(s_in + lane * SP);

        int col = pg;                  // 0..15 < TINW
        int gh  = h0 - 3;
        int off = gh * WGRID + (w0 - 3 + col);

        #pragma unroll 4
        for (int p = pg; p < SPOS; p += 16) {
            const int gw = w0 - 3 + col;
            const bool ok = ((unsigned)gh < (unsigned)HGRID) &&
                            ((unsigned)gw < (unsigned)WGRID);
            const long go = ok ? (long)off : 0;    // clamp OOB address
            cp_async8(sdst + (uint32_t)p * 8u,
                      xb + go * (DIM / 2), ok ? 8 : 0);
            col += 16; off += 16;
            if (col >= TINW) { col -= TINW; gh++; off += WGRID - TINW; }
        }
    }

    // --- 2) Prefused-weight cp.asyncs (coalesced from g_wf) ---
    {
        const int clb = c0 >> 1;
        uint32_t swb = (uint32_t)__cvta_generic_to_shared(s_w);
        #pragma unroll
        for (int i = 0; i < 4; ++i) {
            const int s = tid + i * THREADS;       // 0..1023, need < 896
            if (s < NSLOT * LANES) {
                const int slot = s >> 4;
                const int sl   = s & (LANES - 1);
                cp_async8(swb + (uint32_t)(sl * WP + slot) * 8u,
                          g_wf + slot * (DIM / 2) + clb + sl, 8);
            }
        }
        asm volatile("cp.async.commit_group;" ::: "memory");
    }

    // --- 3) Bias LDG under async flight ---
    const ull bv = g_bs[cl];

    // --- 4) Drain async copies, then block barrier ---
    asm volatile("cp.async.wait_group 0;" ::: "memory");
    __syncthreads();

    // --- Each thread: 2 rows x 16 cols, 2 channels (packed f32x2 math) ---
    const int y   = tid >> 4;           // 0..15 = row pair
    const int or0 = 2 * y;

    const ull* inb = s_in + lane * SP;
    const ull* wb  = s_w + lane * WP;

    ull a0[16], a1[16];
    #pragma unroll
    for (int c = 0; c < 16; ++c) { a0[c] = bv; a1[c] = bv; }

    ull wbuf[8];                        // single weight-row buffer

    #pragma unroll
    for (int ir = 0; ir < 8; ++ir) {    // input rows or0 .. or0+7
        ull in[22];
        {
            const ulonglong2* ip = (const ulonglong2*)(inb + (or0 + ir) * TINW);
            #pragma unroll
            for (int j = 0; j < 11; ++j) {
                ulonglong2 v = ip[j];
                in[2 * j]     = v.x;
                in[2 * j + 1] = v.y;
            }
        }

        // a1 consumes wbuf (= weight row ir-1) before it is overwritten
        if (ir >= 1) {
            #pragma unroll
            for (int kc = 0; kc < 7; ++kc)
                #pragma unroll
                for (int c = 0; c < 16; ++c)
                    a1[c] = fma2(in[c + kc], wbuf[kc], a1[c]);
        }
        // reload wbuf with weight row ir, then feed a0
        if (ir <= 6) {
            const ulonglong2* wp2 = (const ulonglong2*)(wb + ir * 8);
            #pragma unroll
            for (int j = 0; j < 4; ++j) {
                ulonglong2 v = wp2[j];
                wbuf[2 * j]     = v.x;
                wbuf[2 * j + 1] = v.y;
            }
            #pragma unroll
            for (int kc = 0; kc < 7; ++kc)
                #pragma unroll
                for (int c = 0; c < 16; ++c)
                    a0[c] = fma2(in[c + kc], wbuf[kc], a0[c]);
        }
    }

    // --- Store 2 rows x 16 cols ---
    const int row0 = (tokbase + (h0 + or0) * WGRID + w0) * (DIM / 2) + cl;
    const int row1 = row0 + WGRID * (DIM / 2);
    #pragma unroll
    for (int c = 0; c < 16; ++c) {
        o64[row0 + c * (DIM / 2)] = a0[c];
        o64[row1 + c * (DIM / 2)] = a1[c];
    }
}

// ---------------------------------------------------------------------------
extern "C" void kernel_launch(void* const* d_in, const int* in_sizes, int n_in,
                              void* d_out, int out_size) {
    const float* x  = (const float*)d_in[0];
    const float* w7 = (const float*)d_in[1];
    const float* b7 = (const float*)d_in[2];
    const float* w5 = (const float*)d_in[3];
    const float* b5 = (const float*)d_in[4];
    const float* w3 = (const float*)d_in[5];
    const float* b3 = (const float*)d_in[6];
    float* out = (float*)d_out;

    cudaFuncSetAttribute(conv_kernel,
                         cudaFuncAttributeMaxDynamicSharedMemorySize, SMEM_BYTES);

    prep_kernel<<<(PREP_TOT + 255) / 256, 256>>>(x, w7, b7, w5, b5, w3, b3, out);

    dim3 grid(DIM / CT, (HGRID / TILE_H) * (WGRID / TILE_W), BATCH);  // 16,8,16
    conv_kernel<<<grid, THREADS, SMEM_BYTES>>>(x, out);
}

// round 14
// speedup vs baseline: 2.1357x; 1.3064x over previous
#include <cuda_runtime.h>
#include <cuda.h>
#include <cuda_bf16.h>
#include <cstdint>

// Problem constants
#define BATCH 16
#define HGRID 64
#define WGRID 64
#define DIM   512
#define NTOK  (1 + HGRID * WGRID)     // 4097

// Tiling: 32 rows x 16 cols spatial tile, 32 channels (16 ull lanes)
#define CT        32
#define LANES     16
#define TILE_H    32
#define TILE_W    16
#define TINH      (TILE_H + 6)        // 38
#define TINW      (TILE_W + 6)        // 22
#define SPOS      (TINH * TINW)       // 836
#define WP        58                  // weight lane stride: 58*8 mod 128 = 80 -> conflict-free
#define NSLOT     56                  // 7 kr rows x 8 padded kc slots
#define THREADS   256

#define S_IN_ULL   (SPOS * LANES)                 // 13376 (lane-minor [pos][16])
#define S_W_OFF    S_IN_ULL                       // weights after input
#define S_MBAR_OFF (S_IN_ULL + LANES * WP)        // 14304
#define SMEM_ULL   (S_MBAR_OFF + 4)               // 14308
#define SMEM_BYTES (SMEM_ULL * 8)                 // 114464 (x2 blocks fits 228KB)

#define TILE_BYTES (SPOS * LANES * 8)             // 107008

typedef unsigned long long ull;

// One-time fused weights [slot][cl] (slot = kr*8+kc, cl = channel-pair) + bias
__device__ __align__(16) ull g_wf[NSLOT * (DIM / 2)];
__device__ __align__(16) ull g_bs[DIM / 2];

__device__ __forceinline__ ull fma2(ull a, ull b, ull c) {
    ull d;
    asm("fma.rn.f32x2 %0, %1, %2, %3;" : "=l"(d) : "l"(a), "l"(b), "l"(c));
    return d;
}

__device__ __forceinline__ ull pack2(float lo, float hi) {
    ull d;
    asm("mov.b64 %0, {%1, %2};" : "=l"(d) : "f"(lo), "f"(hi));
    return d;
}

__device__ __forceinline__ void cp_async8(uint32_t dst_smem, const void* src) {
    asm volatile("cp.async.ca.shared.global [%0], [%1], 8;"
                 :: "r"(dst_smem), "l"(src));
}

// ---------------------------------------------------------------------------
// Prep: fuse w7+pad(w5)+pad(w3)+identity -> g_wf, biases -> g_bs, cls copy.
// ---------------------------------------------------------------------------
#define PREP_WF  (NSLOT * (DIM / 2))              // 14336
#define PREP_BS  (DIM / 2)                        // 256
#define PREP_CLS (BATCH * (DIM / 2))              // 4096
#define PREP_TOT (PREP_WF + PREP_BS + PREP_CLS)   // 18688

__global__ void prep_kernel(const float* __restrict__ x,
                            const float* __restrict__ w7, const float* __restrict__ b7,
                            const float* __restrict__ w5, const float* __restrict__ b5,
                            const float* __restrict__ w3, const float* __restrict__ b3,
                            float* __restrict__ out) {
    const int idx = blockIdx.x * blockDim.x + threadIdx.x;
    if (idx < PREP_WF) {
        const int slot = idx >> 8;                 // 0..55
        const int cl   = idx & 255;
        const int kr = slot >> 3, kc = slot & 7;
        ull v = 0ull;
        if (kc < 7) {                              // kc==7 is padding
            const int c = 2 * cl;
            const int k = kr * 7 + kc;
            float v0 = w7[c * 49 + k];
            float v1 = w7[(c + 1) * 49 + k];
            if (kr >= 1 && kr <= 5 && kc >= 1 && kc <= 5) {
                const int k5 = (kr - 1) * 5 + (kc - 1);
                v0 += w5[c * 25 + k5];
                v1 += w5[(c + 1) * 25 + k5];
            }
            if (kr >= 2 && kr <= 4 && kc >= 2 && kc <= 4) {
                const int k3 = (kr - 2) * 3 + (kc - 2);
                v0 += w3[c * 9 + k3];
                v1 += w3[(c + 1) * 9 + k3];
            }
            if (kr == 3 && kc == 3) { v0 += 1.0f; v1 += 1.0f; }
            v = pack2(v0, v1);
        }
        g_wf[idx] = v;
    } else if (idx < PREP_WF + PREP_BS) {
        const int cl = idx - PREP_WF;
        const int c  = 2 * cl;
        g_bs[cl] = pack2(b7[c] + b5[c] + b3[c],
                         b7[c + 1] + b5[c + 1] + b3[c + 1]);
    } else if (idx < PREP_TOT) {
        const int i  = idx - PREP_WF - PREP_BS;
        const int b  = i >> 8;
        const int cl = i & 255;
        const size_t off = (size_t)b * NTOK * (DIM / 2) + cl;
        ((ull*)out)[off] = ((const ull*)x)[off];
    }
}

// ---------------------------------------------------------------------------
// Conv: ONE TMA 4D tile load per block (zero-filled halo) + prefused weights
// via cp.async + packed f32x2 math. Each thread: 2 rows x 16 cols x 2 ch.
// smem input is lane-minor [pos][16] (TMA-native); input reads are LDS.64.
// grid: (16 channel groups, 2x4 spatial tiles, 16 batch), 256 threads.
// ---------------------------------------------------------------------------
__global__ void __launch_bounds__(THREADS, 2)
conv_kernel(const __grid_constant__ CUtensorMap tmap, float* __restrict__ out) {
    extern __shared__ ull sm[];
    ull* s_in = sm;                    // [SPOS][LANES]  lane-minor
    ull* s_w  = sm + S_W_OFF;          // [LANES][WP]    lane-major

    const int tid  = threadIdx.x;
    const int lane = tid & (LANES - 1);

    const int c0 = blockIdx.x * CT;
    const int h0 = (blockIdx.y >> 2) * TILE_H;
    const int w0 = (blockIdx.y & 3) * TILE_W;
    const int b  = blockIdx.z;

    ull* o64 = (ull*)out;
    const int cl      = (c0 >> 1) + lane;
    const int tokbase = b * NTOK + 1;              // skip cls token

    const uint32_t smem_base = (uint32_t)__cvta_generic_to_shared(sm);
    const uint32_t mbar      = smem_base + S_MBAR_OFF * 8;

    // --- 1) mbarrier init (one thread) ---
    if (tid == 0) {
        asm volatile("mbarrier.init.shared.b64 [%0], 1;" :: "r"(mbar) : "memory");
    }

    // --- 2) Prefused-weight cp.asyncs (coalesced from g_wf) ---
    {
        const int clb = c0 >> 1;
        const uint32_t swb = smem_base + S_W_OFF * 8;
        #pragma unroll
        for (int i = 0; i < 4; ++i) {
            const int s = tid + i * THREADS;       // need < 896
            if (s < NSLOT * LANES) {
                const int slot = s >> 4;
                const int sl   = s & (LANES - 1);
                cp_async8(swb + (uint32_t)(sl * WP + slot) * 8u,
                          g_wf + slot * (DIM / 2) + clb + sl);
            }
        }
        asm volatile("cp.async.commit_group;" ::: "memory");
    }

    // --- 3) Bias LDG under flight ---
    const ull bv = g_bs[cl];

    // --- 4) Barrier (makes mbarrier init visible), then issue TMA ---
    __syncthreads();
    if (tid == 0) {
        asm volatile("mbarrier.arrive.expect_tx.shared.b64 _, [%0], %1;"
                     :: "r"(mbar), "r"((uint32_t)TILE_BYTES) : "memory");
        asm volatile(
            "cp.async.bulk.tensor.4d.shared::cta.global.tile.mbarrier::complete_tx::bytes "
            "[%0], [%1, {%2, %3, %4, %5}], [%6];"
            :: "r"(smem_base), "l"(&tmap),
               "r"(c0), "r"(w0 - 3), "r"(h0 - 3), "r"(b),
               "r"(mbar)
            : "memory");
    }

    // --- 5) Drain weight cp.asyncs; barrier for weight visibility ---
    asm volatile("cp.async.wait_group 0;" ::: "memory");
    __syncthreads();

    // --- 6) Wait for TMA tile ---
    {
        uint32_t done;
        asm volatile(
            "{\n\t.reg .pred p;\n\t"
            "mbarrier.try_wait.parity.acquire.cta.shared::cta.b64 p, [%1], 0;\n\t"
            "selp.b32 %0, 1, 0, p;\n\t}"
            : "=r"(done) : "r"(mbar) : "memory");
        while (!done) {
            asm volatile(
                "{\n\t.reg .pred p;\n\t"
                "mbarrier.try_wait.parity.acquire.cta.shared::cta.b64 p, [%1], 0, 0x989680;\n\t"
                "selp.b32 %0, 1, 0, p;\n\t}"
                : "=r"(done) : "r"(mbar) : "memory");
        }
    }

    // --- Each thread: 2 rows x 16 cols, 2 channels (packed f32x2 math) ---
    const int y   = tid >> 4;           // 0..15 = row pair
    const int or0 = 2 * y;

    const ull* inb = s_in + lane;       // element (r, c) at inb[(r*TINW+c)*16]
    const ull* wb  = s_w + lane * WP;

    ull a0[16], a1[16];
    #pragma unroll
    for (int c = 0; c < 16; ++c) { a0[c] = bv; a1[c] = bv; }

    ull wbuf[8];                        // single weight-row buffer

    #pragma unroll
    for (int ir = 0; ir < 8; ++ir) {    // input rows or0 .. or0+7
        const ull* rowp = inb + (or0 + ir) * (TINW * LANES);
        ull in[22];
        #pragma unroll
        for (int j = 0; j < 22; ++j)
            in[j] = rowp[j * LANES];

        // a1 consumes wbuf (= weight row ir-1) before it is overwritten
        if (ir >= 1) {
            #pragma unroll
            for (int kc = 0; kc < 7; ++kc)
                #pragma unroll
                for (int c = 0; c < 16; ++c)
                    a1[c] = fma2(in[c + kc], wbuf[kc], a1[c]);
        }
        // reload wbuf with weight row ir, then feed a0
        if (ir <= 6) {
            const ulonglong2* wp2 = (const ulonglong2*)(wb + ir * 8);
            #pragma unroll
            for (int j = 0; j < 4; ++j) {
                ulonglong2 v = wp2[j];
                wbuf[2 * j]     = v.x;
                wbuf[2 * j + 1] = v.y;
            }
            #pragma unroll
            for (int kc = 0; kc < 7; ++kc)
                #pragma unroll
                for (int c = 0; c < 16; ++c)
                    a0[c] = fma2(in[c + kc], wbuf[kc], a0[c]);
        }
    }

    // --- Store 2 rows x 16 cols ---
    const int row0 = (tokbase + (h0 + or0) * WGRID + w0) * (DIM / 2) + cl;
    const int row1 = row0 + WGRID * (DIM / 2);
    #pragma unroll
    for (int c = 0; c < 16; ++c) {
        o64[row0 + c * (DIM / 2)] = a0[c];
        o64[row1 + c * (DIM / 2)] = a1[c];
    }
}

// ---------------------------------------------------------------------------
extern "C" void kernel_launch(void* const* d_in, const int* in_sizes, int n_in,
                              void* d_out, int out_size) {
    const float* x  = (const float*)d_in[0];
    const float* w7 = (const float*)d_in[1];
    const float* b7 = (const float*)d_in[2];
    const float* w5 = (const float*)d_in[3];
    const float* b5 = (const float*)d_in[4];
    const float* w3 = (const float*)d_in[5];
    const float* b3 = (const float*)d_in[6];
    float* out = (float*)d_out;

    // Build the TMA descriptor (host, via driver entry point; no -lcuda).
    typedef CUresult (*EncodeFn)(
        CUtensorMap*, CUtensorMapDataType, cuuint32_t, void*,
        const cuuint64_t*, const cuuint64_t*, const cuuint32_t*,
        const cuuint32_t*, CUtensorMapInterleave, CUtensorMapSwizzle,
        CUtensorMapL2promotion, CUtensorMapFloatOOBfill);
    static EncodeFn encode_fn = nullptr;
    if (!encode_fn) {
        cudaDriverEntryPointQueryResult st;
        void* fp = nullptr;
        cudaGetDriverEntryPoint("cuTensorMapEncodeTiled", &fp,
                                cudaEnableDefault, &st);
        encode_fn = (EncodeFn)fp;
    }
    CUtensorMap tmap;
    {
        // 4D tensor over x (fp32): dim0=channels(512), dim1=w(64), dim2=h(64),
        // dim3=batch(16). Base skips the first cls token; the batch stride
        // (4097 tokens) absorbs each batch's cls slot.
        cuuint64_t dims[4]    = {DIM, WGRID, HGRID, BATCH};
        cuuint64_t strides[3] = {
            (cuuint64_t)DIM * 4,                       // w step: 2048 B
            (cuuint64_t)WGRID * DIM * 4,               // h step: 131072 B
            (cuuint64_t)NTOK * DIM * 4                 // b step: 8390656 B
        };
        cuuint32_t box[4] = {CT, TINW, TINH, 1};       // 32 ch x 22 x 38
        cuuint32_t es[4]  = {1, 1, 1, 1};
        encode_fn(&tmap, CU_TENSOR_MAP_DATA_TYPE_FLOAT32, 4,
                  (void*)(x + DIM),                    // skip batch-0 cls token
                  dims, strides, box, es,
                  CU_TENSOR_MAP_INTERLEAVE_NONE, CU_TENSOR_MAP_SWIZZLE_NONE,
                  CU_TENSOR_MAP_L2_PROMOTION_L2_128B,
                  CU_TENSOR_MAP_FLOAT_OOB_FILL_NONE);
    }

    cudaFuncSetAttribute(conv_kernel,
                         cudaFuncAttributeMaxDynamicSharedMemorySize, SMEM_BYTES);

    prep_kernel<<<(PREP_TOT + 255) / 256, 256>>>(x, w7, b7, w5, b5, w3, b3, out);

    dim3 grid(DIM / CT, (HGRID / TILE_H) * (WGRID / TILE_W), BATCH);  // 16,8,16
    conv_kernel<<<grid, THREADS, SMEM_BYTES>>>(tmap, out);
}